// round 5
// baseline (speedup 1.0000x reference)
#include <cuda_runtime.h>
#include <cuda_bf16.h>
#include <math.h>
#include <stdint.h>

// Problem constants
#define T_TOK 8192
#define DIM   1024
#define FDIM  4096
#define TWOF  8192
#define NEXP  8

// ---------------- helpers ----------------------------------------------------
__device__ __forceinline__ uint32_t smem_u32(const void* p) {
    uint32_t a;
    asm("{ .reg .u64 t; cvta.to.shared.u64 t, %1; cvt.u32.u64 %0, t; }" : "=r"(a) : "l"(p));
    return a;
}
__device__ __forceinline__ void cpa16(uint32_t dst, const void* src, int sz) {
    asm volatile("cp.async.cg.shared.global [%0], [%1], 16, %2;"
                 :: "r"(dst), "l"(src), "r"(sz) : "memory");
}
__device__ __forceinline__ void cpa_commit() {
    asm volatile("cp.async.commit_group;" ::: "memory");
}
__device__ __forceinline__ void ldsm4(uint32_t* r, uint32_t addr) {
    asm volatile("ldmatrix.sync.aligned.m8n8.x4.shared.b16 {%0,%1,%2,%3}, [%4];"
                 : "=r"(r[0]), "=r"(r[1]), "=r"(r[2]), "=r"(r[3]) : "r"(addr));
}
__device__ __forceinline__ void mma16816(float* c, const uint32_t* a, const uint32_t* b) {
    asm volatile("mma.sync.aligned.m16n8k16.row.col.f32.bf16.bf16.f32 "
                 "{%0,%1,%2,%3}, {%4,%5,%6,%7}, {%8,%9}, {%0,%1,%2,%3};"
                 : "+f"(c[0]), "+f"(c[1]), "+f"(c[2]), "+f"(c[3])
                 : "r"(a[0]), "r"(a[1]), "r"(a[2]), "r"(a[3]), "r"(b[0]), "r"(b[1]));
}

// ---------------- scratch (device globals) ----------------------------------
__device__ float g_w[T_TOK];
__device__ int   g_cnt[NEXP];
__device__ float g_ssum[NEXP];
__device__ int   g_tok[NEXP * T_TOK];

__device__ __nv_bfloat16 s_xhi[T_TOK * DIM];
__device__ __nv_bfloat16 s_xlo[T_TOK * DIM];
__device__ __nv_bfloat16 s_w1hi[(size_t)NEXP * TWOF * DIM];   // [e][n][d] K-major
__device__ __nv_bfloat16 s_w1lo[(size_t)NEXP * TWOF * DIM];
__device__ __nv_bfloat16 s_w2hi[(size_t)NEXP * DIM * FDIM];   // [e][d_out][f] K-major
__device__ __nv_bfloat16 s_w2lo[(size_t)NEXP * DIM * FDIM];
__device__ __nv_bfloat16 s_ghi[(size_t)T_TOK * FDIM];
__device__ __nv_bfloat16 s_glo[(size_t)T_TOK * FDIM];

// ---------------- init -------------------------------------------------------
__global__ void k_init() {
    int i = threadIdx.x;
    if (i < NEXP) { g_cnt[i] = 0; g_ssum[i] = 0.0f; }
}

// ---------------- gating + x -> bf16 hi/lo (fused) ---------------------------
__global__ void __launch_bounds__(256) k_gate(const float* __restrict__ x,
                                              const float* __restrict__ Wg,
                                              const float* __restrict__ bg) {
    int warp = threadIdx.x >> 5, lane = threadIdx.x & 31;
    int t = blockIdx.x * 8 + warp;
    const float* xr = x + (size_t)t * DIM;
    float acc[NEXP];
#pragma unroll
    for (int e = 0; e < NEXP; e++) acc[e] = 0.0f;

    const float4* xv4 = (const float4*)xr;
#pragma unroll
    for (int q = 0; q < 8; q++) {
        int idx = lane + q * 32;                 // float4 index in the row
        float4 v = __ldg(xv4 + idx);
        // gating partial sums
        const float* wr = Wg + (idx * 4) * NEXP;
#pragma unroll
        for (int e = 0; e < NEXP; e++)
            acc[e] += v.x * wr[e] + v.y * wr[NEXP + e] + v.z * wr[2 * NEXP + e] + v.w * wr[3 * NEXP + e];
        // hi/lo conversion
        __nv_bfloat16 h0 = __float2bfloat16_rn(v.x), h1 = __float2bfloat16_rn(v.y);
        __nv_bfloat16 h2 = __float2bfloat16_rn(v.z), h3 = __float2bfloat16_rn(v.w);
        __nv_bfloat162 hp0 = __nv_bfloat162(h0, h1), hp1 = __nv_bfloat162(h2, h3);
        __nv_bfloat162 lp0 = __nv_bfloat162(__float2bfloat16_rn(v.x - __bfloat162float(h0)),
                                            __float2bfloat16_rn(v.y - __bfloat162float(h1)));
        __nv_bfloat162 lp1 = __nv_bfloat162(__float2bfloat16_rn(v.z - __bfloat162float(h2)),
                                            __float2bfloat16_rn(v.w - __bfloat162float(h3)));
        size_t o = (size_t)t * DIM + idx * 4;
        *(__nv_bfloat162*)(s_xhi + o)     = hp0;
        *(__nv_bfloat162*)(s_xhi + o + 2) = hp1;
        *(__nv_bfloat162*)(s_xlo + o)     = lp0;
        *(__nv_bfloat162*)(s_xlo + o + 2) = lp1;
    }
#pragma unroll
    for (int e = 0; e < NEXP; e++) {
#pragma unroll
        for (int o = 16; o > 0; o >>= 1) acc[e] += __shfl_xor_sync(0xffffffffu, acc[e], o);
    }
    if (lane == 0) {
        float m = -1e30f;
#pragma unroll
        for (int e = 0; e < NEXP; e++) { acc[e] += bg[e]; m = fmaxf(m, acc[e]); }
        float s = 0.0f, p[NEXP];
#pragma unroll
        for (int e = 0; e < NEXP; e++) { p[e] = expf(acc[e] - m); s += p[e]; }
        int best = 0; float bl = acc[0];
#pragma unroll
        for (int e = 1; e < NEXP; e++) if (acc[e] > bl) { bl = acc[e]; best = e; }
        float w = p[best] / s;
        g_w[t] = w;
        int pos = atomicAdd(&g_cnt[best], 1);
        g_tok[best * T_TOK + pos] = t;
        atomicAdd(&g_ssum[best], w);
    }
}

// ---------------- utilization loss -------------------------------------------
__global__ void k_loss(float* __restrict__ out, int out_size) {
    if (threadIdx.x == 0 && out_size > T_TOK * DIM) {
        float l = 0.0f;
#pragma unroll
        for (int e = 0; e < NEXP; e++) {
            float u = g_ssum[e] / ((float)g_cnt[e] + 1e-8f);
            float d = u - (1.0f / NEXP);
            l += d * d;
        }
        out[T_TOK * DIM] = l;
    }
}

// ---------------- weight transpose+convert [E][R][C] -> [E][C][R] hi/lo ------
__global__ void __launch_bounds__(256) k_cvt_w(const float* __restrict__ W,
                                               __nv_bfloat16* __restrict__ hi,
                                               __nv_bfloat16* __restrict__ lo,
                                               int R, int C) {
    __shared__ float tile[32][33];
    int e = blockIdx.z;
    int c0 = blockIdx.x * 32, r0 = blockIdx.y * 32;
    int tx = threadIdx.x & 31, ty = threadIdx.x >> 5;   // 32 x 8
    const float* Wb = W + (size_t)e * R * C;
#pragma unroll
    for (int i = 0; i < 4; i++) {
        int r = r0 + ty + i * 8;
        tile[ty + i * 8][tx] = Wb[(size_t)r * C + c0 + tx];
    }
    __syncthreads();
    size_t ob = (size_t)e * (size_t)C * R;
#pragma unroll
    for (int i = 0; i < 4; i++) {
        int c = c0 + ty + i * 8;
        float v = tile[tx][ty + i * 8];
        __nv_bfloat16 h = __float2bfloat16_rn(v);
        hi[ob + (size_t)c * R + r0 + tx] = h;
        lo[ob + (size_t)c * R + r0 + tx] = __float2bfloat16_rn(v - __bfloat162float(h));
    }
}

// ---------------- GEMM kernels (mma.sync bf16, 3-term hi/lo) ------------------
// CTA = 128 tokens x 128 cols, K-step 64, 3-stage cp.async pipeline,
// ONE __syncthreads per K-iter.
// GEMM1: B rows interleaved (even = half1 col, odd = half2 col) -> GLU in regs.
#define FB_STRIDE 144
#define FB_TILE   (128 * FB_STRIDE)          // 18432 B
#define STAGE_SZ  (4 * FB_TILE)              // 73728 B (Ah, Al, Bh, Bl)
#define SMEM_DYN  (3 * STAGE_SZ)             // 221184 B

__global__ void __launch_bounds__(256, 1) k_ffn1(const float* __restrict__ bfc) {
    extern __shared__ char dsm[];
    int e = blockIdx.z;
    int cnt = g_cnt[e];
    int m0 = blockIdx.x * 128;
    if (m0 >= cnt) return;
    int n0g = blockIdx.y * 64;               // gated-col base
    int tid = threadIdx.x, wid = tid >> 5, lid = tid & 31;
    uint32_t sb0 = smem_u32(dsm);

    const int NIT = DIM / 64;                // 16
    int lrow = tid >> 1, lpart = tid & 1;
    int tokL = (m0 + lrow < cnt) ? g_tok[e * T_TOK + m0 + lrow] : -1;
    const char* aH = (const char*)(s_xhi + (size_t)(tokL < 0 ? 0 : tokL) * DIM);
    const char* aL = (const char*)(s_xlo + (size_t)(tokL < 0 ? 0 : tokL) * DIM);
    size_t bro = (size_t)e * TWOF + (size_t)(lrow & 1) * FDIM + n0g + (lrow >> 1);
    const char* bH = (const char*)(s_w1hi + bro * DIM);
    const char* bL = (const char*)(s_w1lo + bro * DIM);
    int asz = (tokL >= 0) ? 16 : 0;
    uint32_t drow = sb0 + lrow * FB_STRIDE;

    auto issue = [&](int slot, int it) {
        int kb = it * 128;                    // 64 k * 2B
        uint32_t db = drow + slot * STAGE_SZ;
#pragma unroll
        for (int i = 0; i < 4; i++) {
            int co = lpart * 64 + i * 16;
            cpa16(db + 0 * FB_TILE + co, aH + kb + co, asz);
            cpa16(db + 1 * FB_TILE + co, aL + kb + co, asz);
            cpa16(db + 2 * FB_TILE + co, bH + kb + co, 16);
            cpa16(db + 3 * FB_TILE + co, bL + kb + co, 16);
        }
        cpa_commit();
    };

    int lane = lid;
    int wm = (wid & 3) * 32, wn = (wid >> 2) * 64;
    int lA_r = (lane & 7) + ((lane >> 3) & 1) * 8, lA_c = lane >> 4;
    int lB_r = (lane & 7) + ((lane >> 4) & 1) * 8, lB_c = (lane >> 3) & 1;

    float acc[2][8][4];
#pragma unroll
    for (int i = 0; i < 2; i++)
#pragma unroll
        for (int j = 0; j < 8; j++)
#pragma unroll
            for (int q = 0; q < 4; q++) acc[i][j][q] = 0.0f;

    issue(0, 0);
    issue(1, 1);
    int slot = 0;
    for (int it = 0; it < NIT; it++) {
        if (it + 1 < NIT) asm volatile("cp.async.wait_group 1;" ::: "memory");
        else              asm volatile("cp.async.wait_group 0;" ::: "memory");
        __syncthreads();
        if (it + 2 < NIT) issue((it + 2) % 3, it + 2);

        uint32_t Ah = sb0 + slot * STAGE_SZ;
        uint32_t Al = Ah + FB_TILE, Bh = Ah + 2 * FB_TILE, Bl = Ah + 3 * FB_TILE;
#pragma unroll
        for (int k16 = 0; k16 < 4; k16++) {
            uint32_t ah[2][4], al[2][4];
#pragma unroll
            for (int i = 0; i < 2; i++) {
                uint32_t ao = (uint32_t)((wm + i * 16 + lA_r) * FB_STRIDE + (k16 * 2 + lA_c) * 16);
                ldsm4(ah[i], Ah + ao);
                ldsm4(al[i], Al + ao);
            }
            uint32_t bh[8][2], bl[8][2];
#pragma unroll
            for (int j2 = 0; j2 < 4; j2++) {
                uint32_t bo = (uint32_t)((wn + j2 * 16 + lB_r) * FB_STRIDE + (k16 * 2 + lB_c) * 16);
                uint32_t t4[4];
                ldsm4(t4, Bh + bo);
                bh[2 * j2][0] = t4[0]; bh[2 * j2][1] = t4[1];
                bh[2 * j2 + 1][0] = t4[2]; bh[2 * j2 + 1][1] = t4[3];
                ldsm4(t4, Bl + bo);
                bl[2 * j2][0] = t4[0]; bl[2 * j2][1] = t4[1];
                bl[2 * j2 + 1][0] = t4[2]; bl[2 * j2 + 1][1] = t4[3];
            }
#pragma unroll
            for (int i = 0; i < 2; i++)
#pragma unroll
                for (int j = 0; j < 8; j++) {
                    mma16816(acc[i][j], ah[i], bh[j]);
                    mma16816(acc[i][j], al[i], bh[j]);
                    mma16816(acc[i][j], ah[i], bl[j]);
                }
        }
        slot = (slot + 1) % 3;
    }

    // epilogue: thread holds (h1,h2) col pairs -> GLU -> hi/lo store
#pragma unroll
    for (int i = 0; i < 2; i++) {
        int row0 = wm + i * 16 + (lane >> 2);
        int tok0 = (m0 + row0 < cnt) ? g_tok[e * T_TOK + m0 + row0] : -1;
        int tok1 = (m0 + row0 + 8 < cnt) ? g_tok[e * T_TOK + m0 + row0 + 8] : -1;
#pragma unroll
        for (int j = 0; j < 8; j++) {
            int gcol = n0g + wn / 2 + j * 4 + (lane & 3);
            float b1 = __ldg(bfc + (size_t)e * TWOF + gcol);
            float b2 = __ldg(bfc + (size_t)e * TWOF + FDIM + gcol);
            if (tok0 >= 0) {
                float h1 = acc[i][j][0] + b1, h2 = acc[i][j][1] + b2;
                float g = h1 * (0.5f * h2 * (1.0f + erff(h2 * 0.70710678118654752f)));
                __nv_bfloat16 h = __float2bfloat16_rn(g);
                s_ghi[(size_t)tok0 * FDIM + gcol] = h;
                s_glo[(size_t)tok0 * FDIM + gcol] = __float2bfloat16_rn(g - __bfloat162float(h));
            }
            if (tok1 >= 0) {
                float h1 = acc[i][j][2] + b1, h2 = acc[i][j][3] + b2;
                float g = h1 * (0.5f * h2 * (1.0f + erff(h2 * 0.70710678118654752f)));
                __nv_bfloat16 h = __float2bfloat16_rn(g);
                s_ghi[(size_t)tok1 * FDIM + gcol] = h;
                s_glo[(size_t)tok1 * FDIM + gcol] = __float2bfloat16_rn(g - __bfloat162float(h));
            }
        }
    }
}

__global__ void __launch_bounds__(256, 1) k_ffn2(const float* __restrict__ bout,
                                                 float* __restrict__ out) {
    extern __shared__ char dsm[];
    int e = blockIdx.z;
    int cnt = g_cnt[e];
    int m0 = blockIdx.x * 128;
    if (m0 >= cnt) return;
    int n0 = blockIdx.y * 128;
    int tid = threadIdx.x, wid = tid >> 5, lid = tid & 31;
    uint32_t sb0 = smem_u32(dsm);

    const int NIT = FDIM / 64;               // 64
    int lrow = tid >> 1, lpart = tid & 1;
    int tokL = (m0 + lrow < cnt) ? g_tok[e * T_TOK + m0 + lrow] : -1;
    const char* aH = (const char*)(s_ghi + (size_t)(tokL < 0 ? 0 : tokL) * FDIM);
    const char* aL = (const char*)(s_glo + (size_t)(tokL < 0 ? 0 : tokL) * FDIM);
    const char* bH = (const char*)(s_w2hi + ((size_t)e * DIM + n0 + lrow) * FDIM);
    const char* bL = (const char*)(s_w2lo + ((size_t)e * DIM + n0 + lrow) * FDIM);
    int asz = (tokL >= 0) ? 16 : 0;
    uint32_t drow = sb0 + lrow * FB_STRIDE;

    auto issue = [&](int slot, int it) {
        int kb = it * 128;
        uint32_t db = drow + slot * STAGE_SZ;
#pragma unroll
        for (int i = 0; i < 4; i++) {
            int co = lpart * 64 + i * 16;
            cpa16(db + 0 * FB_TILE + co, aH + kb + co, asz);
            cpa16(db + 1 * FB_TILE + co, aL + kb + co, asz);
            cpa16(db + 2 * FB_TILE + co, bH + kb + co, 16);
            cpa16(db + 3 * FB_TILE + co, bL + kb + co, 16);
        }
        cpa_commit();
    };

    int lane = lid;
    int wm = (wid & 3) * 32, wn = (wid >> 2) * 64;
    int lA_r = (lane & 7) + ((lane >> 3) & 1) * 8, lA_c = lane >> 4;
    int lB_r = (lane & 7) + ((lane >> 4) & 1) * 8, lB_c = (lane >> 3) & 1;

    float acc[2][8][4];
#pragma unroll
    for (int i = 0; i < 2; i++)
#pragma unroll
        for (int j = 0; j < 8; j++)
#pragma unroll
            for (int q = 0; q < 4; q++) acc[i][j][q] = 0.0f;

    issue(0, 0);
    issue(1, 1);
    int slot = 0;
    for (int it = 0; it < NIT; it++) {
        if (it + 1 < NIT) asm volatile("cp.async.wait_group 1;" ::: "memory");
        else              asm volatile("cp.async.wait_group 0;" ::: "memory");
        __syncthreads();
        if (it + 2 < NIT) issue((it + 2) % 3, it + 2);

        uint32_t Ah = sb0 + slot * STAGE_SZ;
        uint32_t Al = Ah + FB_TILE, Bh = Ah + 2 * FB_TILE, Bl = Ah + 3 * FB_TILE;
#pragma unroll
        for (int k16 = 0; k16 < 4; k16++) {
            uint32_t ah[2][4], al[2][4];
#pragma unroll
            for (int i = 0; i < 2; i++) {
                uint32_t ao = (uint32_t)((wm + i * 16 + lA_r) * FB_STRIDE + (k16 * 2 + lA_c) * 16);
                ldsm4(ah[i], Ah + ao);
                ldsm4(al[i], Al + ao);
            }
            uint32_t bh[8][2], bl[8][2];
#pragma unroll
            for (int j2 = 0; j2 < 4; j2++) {
                uint32_t bo = (uint32_t)((wn + j2 * 16 + lB_r) * FB_STRIDE + (k16 * 2 + lB_c) * 16);
                uint32_t t4[4];
                ldsm4(t4, Bh + bo);
                bh[2 * j2][0] = t4[0]; bh[2 * j2][1] = t4[1];
                bh[2 * j2 + 1][0] = t4[2]; bh[2 * j2 + 1][1] = t4[3];
                ldsm4(t4, Bl + bo);
                bl[2 * j2][0] = t4[0]; bl[2 * j2][1] = t4[1];
                bl[2 * j2 + 1][0] = t4[2]; bl[2 * j2 + 1][1] = t4[3];
            }
#pragma unroll
            for (int i = 0; i < 2; i++)
#pragma unroll
                for (int j = 0; j < 8; j++) {
                    mma16816(acc[i][j], ah[i], bh[j]);
                    mma16816(acc[i][j], al[i], bh[j]);
                    mma16816(acc[i][j], ah[i], bl[j]);
                }
        }
        slot = (slot + 1) % 3;
    }

#pragma unroll
    for (int i = 0; i < 2; i++) {
        int row0 = wm + i * 16 + (lane >> 2);
        int tok0 = (m0 + row0 < cnt) ? g_tok[e * T_TOK + m0 + row0] : -1;
        int tok1 = (m0 + row0 + 8 < cnt) ? g_tok[e * T_TOK + m0 + row0 + 8] : -1;
        float w0 = (tok0 >= 0) ? g_w[tok0] : 0.0f;
        float w1 = (tok1 >= 0) ? g_w[tok1] : 0.0f;
#pragma unroll
        for (int j = 0; j < 8; j++) {
            int col = n0 + wn + j * 8 + 2 * (lane & 3);
            float b0 = __ldg(bout + (size_t)e * DIM + col);
            float b1 = __ldg(bout + (size_t)e * DIM + col + 1);
            if (tok0 >= 0) {
                float2 v = make_float2(w0 * (acc[i][j][0] + b0), w0 * (acc[i][j][1] + b1));
                *(float2*)(out + (size_t)tok0 * DIM + col) = v;
            }
            if (tok1 >= 0) {
                float2 v = make_float2(w1 * (acc[i][j][2] + b0), w1 * (acc[i][j][3] + b1));
                *(float2*)(out + (size_t)tok1 * DIM + col) = v;
            }
        }
    }
}

// ---------------- launch ------------------------------------------------------
extern "C" void kernel_launch(void* const* d_in, const int* in_sizes, int n_in,
                              void* d_out, int out_size) {
    const float* x    = (const float*)d_in[0];
    const float* Wg   = (const float*)d_in[1];
    const float* bg   = (const float*)d_in[2];
    const float* Wfc  = (const float*)d_in[3];
    const float* bfc  = (const float*)d_in[4];
    const float* Wout = (const float*)d_in[5];
    const float* bout = (const float*)d_in[6];
    float* out = (float*)d_out;

    cudaFuncSetAttribute(k_ffn1, cudaFuncAttributeMaxDynamicSharedMemorySize, SMEM_DYN);
    cudaFuncSetAttribute(k_ffn2, cudaFuncAttributeMaxDynamicSharedMemorySize, SMEM_DYN);

    __nv_bfloat16 *w1h, *w1l, *w2h, *w2l;
    cudaGetSymbolAddress((void**)&w1h, s_w1hi);
    cudaGetSymbolAddress((void**)&w1l, s_w1lo);
    cudaGetSymbolAddress((void**)&w2h, s_w2hi);
    cudaGetSymbolAddress((void**)&w2l, s_w2lo);

    // Launch order chosen so k_ffn1 is the 4th launch (ncu capture slot).
    k_init<<<1, 32>>>();                                   // 1
    k_gate<<<T_TOK / 8, 256>>>(x, Wg, bg);                 // 2 (gating + x hi/lo)
    {
        dim3 b(256);
        dim3 gw1(TWOF / 32, DIM / 32, NEXP);
        k_cvt_w<<<gw1, b>>>(Wfc, w1h, w1l, DIM, TWOF);     // 3
    }
    dim3 g1(T_TOK / 128, FDIM / 64, NEXP);                 // (64, 64, 8)
    k_ffn1<<<g1, 256, SMEM_DYN>>>(bfc);                    // 4  <-- profiled
    k_loss<<<1, 32>>>(out, out_size);                      // 5
    {
        dim3 b(256);
        dim3 gw2(DIM / 32, FDIM / 32, NEXP);
        k_cvt_w<<<gw2, b>>>(Wout, w2h, w2l, FDIM, DIM);    // 6
    }
    dim3 g2(T_TOK / 128, DIM / 128, NEXP);                 // (64, 8, 8)
    k_ffn2<<<g2, 256, SMEM_DYN>>>(bout, out);              // 7
}

// round 6
// speedup vs baseline: 1.0992x; 1.0992x over previous
#include <cuda_runtime.h>
#include <cuda_bf16.h>
#include <math.h>
#include <stdint.h>

// Problem constants
#define T_TOK 8192
#define DIM   1024
#define FDIM  4096
#define TWOF  8192
#define NEXP  8

// ---------------- helpers ----------------------------------------------------
__device__ __forceinline__ uint32_t smem_u32(const void* p) {
    uint32_t a;
    asm("{ .reg .u64 t; cvta.to.shared.u64 t, %1; cvt.u32.u64 %0, t; }" : "=r"(a) : "l"(p));
    return a;
}
__device__ __forceinline__ void cpa16(uint32_t dst, const void* src, int sz) {
    asm volatile("cp.async.cg.shared.global [%0], [%1], 16, %2;"
                 :: "r"(dst), "l"(src), "r"(sz) : "memory");
}
__device__ __forceinline__ void cpa_commit() {
    asm volatile("cp.async.commit_group;" ::: "memory");
}
__device__ __forceinline__ void ldsm4(uint32_t* r, uint32_t addr) {
    asm volatile("ldmatrix.sync.aligned.m8n8.x4.shared.b16 {%0,%1,%2,%3}, [%4];"
                 : "=r"(r[0]), "=r"(r[1]), "=r"(r[2]), "=r"(r[3]) : "r"(addr));
}
__device__ __forceinline__ void mma16816(float* c, const uint32_t* a, const uint32_t* b) {
    asm volatile("mma.sync.aligned.m16n8k16.row.col.f32.bf16.bf16.f32 "
                 "{%0,%1,%2,%3}, {%4,%5,%6,%7}, {%8,%9}, {%0,%1,%2,%3};"
                 : "+f"(c[0]), "+f"(c[1]), "+f"(c[2]), "+f"(c[3])
                 : "r"(a[0]), "r"(a[1]), "r"(a[2]), "r"(a[3]), "r"(b[0]), "r"(b[1]));
}

// ---------------- scratch (device globals) ----------------------------------
__device__ float g_w[T_TOK];
__device__ int   g_cnt[NEXP];
__device__ float g_ssum[NEXP];
__device__ int   g_tok[NEXP * T_TOK];

__device__ __nv_bfloat16 s_xhi[T_TOK * DIM];
__device__ __nv_bfloat16 s_xlo[T_TOK * DIM];
__device__ __nv_bfloat16 s_w1hi[(size_t)NEXP * TWOF * DIM];   // [e][n][d] K-major
__device__ __nv_bfloat16 s_w1lo[(size_t)NEXP * TWOF * DIM];
__device__ __nv_bfloat16 s_w2hi[(size_t)NEXP * DIM * FDIM];   // [e][d_out][f] K-major
__device__ __nv_bfloat16 s_w2lo[(size_t)NEXP * DIM * FDIM];
__device__ __nv_bfloat16 s_ghi[(size_t)T_TOK * FDIM];
__device__ __nv_bfloat16 s_glo[(size_t)T_TOK * FDIM];

// ---------------- init -------------------------------------------------------
__global__ void k_init() {
    int i = threadIdx.x;
    if (i < NEXP) { g_cnt[i] = 0; g_ssum[i] = 0.0f; }
}

// ---------------- gating + x -> bf16 hi/lo (fused) ---------------------------
__global__ void __launch_bounds__(256) k_gate(const float* __restrict__ x,
                                              const float* __restrict__ Wg,
                                              const float* __restrict__ bg) {
    int warp = threadIdx.x >> 5, lane = threadIdx.x & 31;
    int t = blockIdx.x * 8 + warp;
    const float* xr = x + (size_t)t * DIM;
    float acc[NEXP];
#pragma unroll
    for (int e = 0; e < NEXP; e++) acc[e] = 0.0f;

    const float4* xv4 = (const float4*)xr;
#pragma unroll
    for (int q = 0; q < 8; q++) {
        int idx = lane + q * 32;
        float4 v = __ldg(xv4 + idx);
        const float* wr = Wg + (idx * 4) * NEXP;
#pragma unroll
        for (int e = 0; e < NEXP; e++)
            acc[e] += v.x * wr[e] + v.y * wr[NEXP + e] + v.z * wr[2 * NEXP + e] + v.w * wr[3 * NEXP + e];
        __nv_bfloat16 h0 = __float2bfloat16_rn(v.x), h1 = __float2bfloat16_rn(v.y);
        __nv_bfloat16 h2 = __float2bfloat16_rn(v.z), h3 = __float2bfloat16_rn(v.w);
        __nv_bfloat162 hp0 = __nv_bfloat162(h0, h1), hp1 = __nv_bfloat162(h2, h3);
        __nv_bfloat162 lp0 = __nv_bfloat162(__float2bfloat16_rn(v.x - __bfloat162float(h0)),
                                            __float2bfloat16_rn(v.y - __bfloat162float(h1)));
        __nv_bfloat162 lp1 = __nv_bfloat162(__float2bfloat16_rn(v.z - __bfloat162float(h2)),
                                            __float2bfloat16_rn(v.w - __bfloat162float(h3)));
        size_t o = (size_t)t * DIM + idx * 4;
        *(__nv_bfloat162*)(s_xhi + o)     = hp0;
        *(__nv_bfloat162*)(s_xhi + o + 2) = hp1;
        *(__nv_bfloat162*)(s_xlo + o)     = lp0;
        *(__nv_bfloat162*)(s_xlo + o + 2) = lp1;
    }
#pragma unroll
    for (int e = 0; e < NEXP; e++) {
#pragma unroll
        for (int o = 16; o > 0; o >>= 1) acc[e] += __shfl_xor_sync(0xffffffffu, acc[e], o);
    }
    if (lane == 0) {
        float m = -1e30f;
#pragma unroll
        for (int e = 0; e < NEXP; e++) { acc[e] += bg[e]; m = fmaxf(m, acc[e]); }
        float s = 0.0f, p[NEXP];
#pragma unroll
        for (int e = 0; e < NEXP; e++) { p[e] = expf(acc[e] - m); s += p[e]; }
        int best = 0; float bl = acc[0];
#pragma unroll
        for (int e = 1; e < NEXP; e++) if (acc[e] > bl) { bl = acc[e]; best = e; }
        float w = p[best] / s;
        g_w[t] = w;
        int pos = atomicAdd(&g_cnt[best], 1);
        g_tok[best * T_TOK + pos] = t;
        atomicAdd(&g_ssum[best], w);
    }
}

// ---------------- utilization loss -------------------------------------------
__global__ void k_loss(float* __restrict__ out, int out_size) {
    if (threadIdx.x == 0 && out_size > T_TOK * DIM) {
        float l = 0.0f;
#pragma unroll
        for (int e = 0; e < NEXP; e++) {
            float u = g_ssum[e] / ((float)g_cnt[e] + 1e-8f);
            float d = u - (1.0f / NEXP);
            l += d * d;
        }
        out[T_TOK * DIM] = l;
    }
}

// ---------------- weight transpose+convert [E][R][C] -> [E][C][R] hi/lo ------
__global__ void __launch_bounds__(256) k_cvt_w(const float* __restrict__ W,
                                               __nv_bfloat16* __restrict__ hi,
                                               __nv_bfloat16* __restrict__ lo,
                                               int R, int C) {
    __shared__ float tile[32][33];
    int e = blockIdx.z;
    int c0 = blockIdx.x * 32, r0 = blockIdx.y * 32;
    int tx = threadIdx.x & 31, ty = threadIdx.x >> 5;
    const float* Wb = W + (size_t)e * R * C;
#pragma unroll
    for (int i = 0; i < 4; i++) {
        int r = r0 + ty + i * 8;
        tile[ty + i * 8][tx] = Wb[(size_t)r * C + c0 + tx];
    }
    __syncthreads();
    size_t ob = (size_t)e * (size_t)C * R;
#pragma unroll
    for (int i = 0; i < 4; i++) {
        int c = c0 + ty + i * 8;
        float v = tile[tx][ty + i * 8];
        __nv_bfloat16 h = __float2bfloat16_rn(v);
        hi[ob + (size_t)c * R + r0 + tx] = h;
        lo[ob + (size_t)c * R + r0 + tx] = __float2bfloat16_rn(v - __bfloat162float(h));
    }
}

// ---------------- GEMM kernels (mma.sync bf16, 3-term hi/lo) ------------------
// CTA = 64 tokens x 128 cols, K-step 32, 3-stage pipeline, issue-before-wait,
// 2 CTAs/SM (92 KB smem, <=128 regs). Warp grid 2x4, warp tile 32m x 32n.
// GEMM1: B rows interleaved (even = half1 col, odd = half2 col) -> GLU in regs.
#define KBYTES   64                        // 32 k * 2B
#define ST       80                        // row stride (64B data + 16 pad)
#define A_TILE   (64 * ST)                 // 5120
#define B_TILE   (128 * ST)                // 10240
#define STAGE_SZ (2 * A_TILE + 2 * B_TILE) // 30720
#define OFF_AH   0
#define OFF_AL   A_TILE
#define OFF_BH   (2 * A_TILE)
#define OFF_BL   (2 * A_TILE + B_TILE)
#define SMEM_DYN (3 * STAGE_SZ)            // 92160

struct FfnCtx {
    const char *aH, *aL, *bH, *bL;
    int asz;
    uint32_t a_dst, b_dst;                 // smem offsets within a stage
};

__device__ __forceinline__ void ffn_issue(const FfnCtx& c, uint32_t sb0, int slot, int it) {
    int kb = it * KBYTES;
    uint32_t st = sb0 + slot * STAGE_SZ;
    // A: this thread's row (t>>2), one 16B chunk (t&3)
    cpa16(st + OFF_AH + c.a_dst, c.aH + kb + ((c.a_dst % ST)), 0);  // placeholder (never used)
}

// (loading is inlined in the kernels; struct above unused — kept minimal)

__global__ void __launch_bounds__(256, 2) k_ffn1(const float* __restrict__ bfc) {
    extern __shared__ char dsm[];
    int e = blockIdx.z;
    int cnt = g_cnt[e];
    int m0 = blockIdx.x * 64;
    if (m0 >= cnt) return;
    int n0g = blockIdx.y * 64;               // gated-col base (128 raw cols)
    int tid = threadIdx.x, wid = tid >> 5, lane = tid & 31;
    uint32_t sb0 = smem_u32(dsm);

    const int NIT = DIM / 32;                // 32
    // A loading: row = tid>>2 (0..63), chunk = tid&3
    int arow = tid >> 2, apart = tid & 3;
    int tokL = (m0 + arow < cnt) ? g_tok[e * T_TOK + m0 + arow] : -1;
    const char* aH = (const char*)(s_xhi + (size_t)(tokL < 0 ? 0 : tokL) * DIM);
    const char* aL = (const char*)(s_xlo + (size_t)(tokL < 0 ? 0 : tokL) * DIM);
    int asz = (tokL >= 0) ? 16 : 0;
    uint32_t a_off = (uint32_t)(arow * ST + apart * 16);
    // B loading: row = tid>>1 (0..127), half = tid&1 (two chunks)
    int brow = tid >> 1, bpart = tid & 1;
    size_t bro = (size_t)e * TWOF + (size_t)(brow & 1) * FDIM + n0g + (brow >> 1);
    const char* bH = (const char*)(s_w1hi + bro * DIM);
    const char* bL = (const char*)(s_w1lo + bro * DIM);
    uint32_t b_off = (uint32_t)(brow * ST + bpart * 32);

    auto issue = [&](int slot, int it) {
        int kb = it * KBYTES;
        uint32_t st = sb0 + slot * STAGE_SZ;
        cpa16(st + OFF_AH + a_off, aH + kb + apart * 16, asz);
        cpa16(st + OFF_AL + a_off, aL + kb + apart * 16, asz);
        cpa16(st + OFF_BH + b_off,      bH + kb + bpart * 32,      16);
        cpa16(st + OFF_BH + b_off + 16, bH + kb + bpart * 32 + 16, 16);
        cpa16(st + OFF_BL + b_off,      bL + kb + bpart * 32,      16);
        cpa16(st + OFF_BL + b_off + 16, bL + kb + bpart * 32 + 16, 16);
        cpa_commit();
    };

    int wm = (wid >> 2) * 32, wn = (wid & 3) * 32;
    int lA_r = (lane & 7) + ((lane >> 3) & 1) * 8, lA_c = lane >> 4;
    int lB_r = (lane & 7) + ((lane >> 4) & 1) * 8, lB_c = (lane >> 3) & 1;

    float acc[2][4][4];
#pragma unroll
    for (int i = 0; i < 2; i++)
#pragma unroll
        for (int j = 0; j < 4; j++)
#pragma unroll
            for (int q = 0; q < 4; q++) acc[i][j][q] = 0.0f;

    issue(0, 0);
    issue(1, 1);
    int slot = 0;
    for (int it = 0; it < NIT; it++) {
        if (it + 2 < NIT) {
            issue((it + 2) % 3, it + 2);
            asm volatile("cp.async.wait_group 2;" ::: "memory");
        } else if (it + 1 < NIT) {
            asm volatile("cp.async.wait_group 1;" ::: "memory");
        } else {
            asm volatile("cp.async.wait_group 0;" ::: "memory");
        }
        __syncthreads();

        uint32_t stg = sb0 + slot * STAGE_SZ;
#pragma unroll
        for (int k16 = 0; k16 < 2; k16++) {
            uint32_t ah[2][4], al[2][4];
#pragma unroll
            for (int i = 0; i < 2; i++) {
                uint32_t ao = (uint32_t)((wm + i * 16 + lA_r) * ST + (k16 * 2 + lA_c) * 16);
                ldsm4(ah[i], stg + OFF_AH + ao);
                ldsm4(al[i], stg + OFF_AL + ao);
            }
            uint32_t bh[4][2], bl[4][2];
#pragma unroll
            for (int j2 = 0; j2 < 2; j2++) {
                uint32_t bo = (uint32_t)((wn + j2 * 16 + lB_r) * ST + (k16 * 2 + lB_c) * 16);
                uint32_t t4[4];
                ldsm4(t4, stg + OFF_BH + bo);
                bh[2 * j2][0] = t4[0]; bh[2 * j2][1] = t4[1];
                bh[2 * j2 + 1][0] = t4[2]; bh[2 * j2 + 1][1] = t4[3];
                ldsm4(t4, stg + OFF_BL + bo);
                bl[2 * j2][0] = t4[0]; bl[2 * j2][1] = t4[1];
                bl[2 * j2 + 1][0] = t4[2]; bl[2 * j2 + 1][1] = t4[3];
            }
#pragma unroll
            for (int i = 0; i < 2; i++)
#pragma unroll
                for (int j = 0; j < 4; j++) {
                    mma16816(acc[i][j], ah[i], bh[j]);
                    mma16816(acc[i][j], al[i], bh[j]);
                    mma16816(acc[i][j], ah[i], bl[j]);
                }
        }
        __syncthreads();
        slot = (slot + 1) % 3;
    }

    // epilogue: (h1,h2) col pairs -> GLU -> hi/lo store
#pragma unroll
    for (int i = 0; i < 2; i++) {
        int row0 = wm + i * 16 + (lane >> 2);
        int tok0 = (m0 + row0 < cnt) ? g_tok[e * T_TOK + m0 + row0] : -1;
        int tok1 = (m0 + row0 + 8 < cnt) ? g_tok[e * T_TOK + m0 + row0 + 8] : -1;
#pragma unroll
        for (int j = 0; j < 4; j++) {
            int gcol = n0g + wn / 2 + j * 4 + (lane & 3);
            float b1 = __ldg(bfc + (size_t)e * TWOF + gcol);
            float b2 = __ldg(bfc + (size_t)e * TWOF + FDIM + gcol);
            if (tok0 >= 0) {
                float h1 = acc[i][j][0] + b1, h2 = acc[i][j][1] + b2;
                float g = h1 * (0.5f * h2 * (1.0f + erff(h2 * 0.70710678118654752f)));
                __nv_bfloat16 h = __float2bfloat16_rn(g);
                s_ghi[(size_t)tok0 * FDIM + gcol] = h;
                s_glo[(size_t)tok0 * FDIM + gcol] = __float2bfloat16_rn(g - __bfloat162float(h));
            }
            if (tok1 >= 0) {
                float h1 = acc[i][j][2] + b1, h2 = acc[i][j][3] + b2;
                float g = h1 * (0.5f * h2 * (1.0f + erff(h2 * 0.70710678118654752f)));
                __nv_bfloat16 h = __float2bfloat16_rn(g);
                s_ghi[(size_t)tok1 * FDIM + gcol] = h;
                s_glo[(size_t)tok1 * FDIM + gcol] = __float2bfloat16_rn(g - __bfloat162float(h));
            }
        }
    }
}

__global__ void __launch_bounds__(256, 2) k_ffn2(const float* __restrict__ bout,
                                                 float* __restrict__ out) {
    extern __shared__ char dsm[];
    int e = blockIdx.z;
    int cnt = g_cnt[e];
    int m0 = blockIdx.x * 64;
    if (m0 >= cnt) return;
    int n0 = blockIdx.y * 128;
    int tid = threadIdx.x, wid = tid >> 5, lane = tid & 31;
    uint32_t sb0 = smem_u32(dsm);

    const int NIT = FDIM / 32;               // 128
    int arow = tid >> 2, apart = tid & 3;
    int tokL = (m0 + arow < cnt) ? g_tok[e * T_TOK + m0 + arow] : -1;
    const char* aH = (const char*)(s_ghi + (size_t)(tokL < 0 ? 0 : tokL) * FDIM);
    const char* aL = (const char*)(s_glo + (size_t)(tokL < 0 ? 0 : tokL) * FDIM);
    int asz = (tokL >= 0) ? 16 : 0;
    uint32_t a_off = (uint32_t)(arow * ST + apart * 16);
    int brow = tid >> 1, bpart = tid & 1;
    const char* bH = (const char*)(s_w2hi + ((size_t)e * DIM + n0 + brow) * FDIM);
    const char* bL = (const char*)(s_w2lo + ((size_t)e * DIM + n0 + brow) * FDIM);
    uint32_t b_off = (uint32_t)(brow * ST + bpart * 32);

    auto issue = [&](int slot, int it) {
        int kb = it * KBYTES;
        uint32_t st = sb0 + slot * STAGE_SZ;
        cpa16(st + OFF_AH + a_off, aH + kb + apart * 16, asz);
        cpa16(st + OFF_AL + a_off, aL + kb + apart * 16, asz);
        cpa16(st + OFF_BH + b_off,      bH + kb + bpart * 32,      16);
        cpa16(st + OFF_BH + b_off + 16, bH + kb + bpart * 32 + 16, 16);
        cpa16(st + OFF_BL + b_off,      bL + kb + bpart * 32,      16);
        cpa16(st + OFF_BL + b_off + 16, bL + kb + bpart * 32 + 16, 16);
        cpa_commit();
    };

    int wm = (wid >> 2) * 32, wn = (wid & 3) * 32;
    int lA_r = (lane & 7) + ((lane >> 3) & 1) * 8, lA_c = lane >> 4;
    int lB_r = (lane & 7) + ((lane >> 4) & 1) * 8, lB_c = (lane >> 3) & 1;

    float acc[2][4][4];
#pragma unroll
    for (int i = 0; i < 2; i++)
#pragma unroll
        for (int j = 0; j < 4; j++)
#pragma unroll
            for (int q = 0; q < 4; q++) acc[i][j][q] = 0.0f;

    issue(0, 0);
    issue(1, 1);
    int slot = 0;
    for (int it = 0; it < NIT; it++) {
        if (it + 2 < NIT) {
            issue((it + 2) % 3, it + 2);
            asm volatile("cp.async.wait_group 2;" ::: "memory");
        } else if (it + 1 < NIT) {
            asm volatile("cp.async.wait_group 1;" ::: "memory");
        } else {
            asm volatile("cp.async.wait_group 0;" ::: "memory");
        }
        __syncthreads();

        uint32_t stg = sb0 + slot * STAGE_SZ;
#pragma unroll
        for (int k16 = 0; k16 < 2; k16++) {
            uint32_t ah[2][4], al[2][4];
#pragma unroll
            for (int i = 0; i < 2; i++) {
                uint32_t ao = (uint32_t)((wm + i * 16 + lA_r) * ST + (k16 * 2 + lA_c) * 16);
                ldsm4(ah[i], stg + OFF_AH + ao);
                ldsm4(al[i], stg + OFF_AL + ao);
            }
            uint32_t bh[4][2], bl[4][2];
#pragma unroll
            for (int j2 = 0; j2 < 2; j2++) {
                uint32_t bo = (uint32_t)((wn + j2 * 16 + lB_r) * ST + (k16 * 2 + lB_c) * 16);
                uint32_t t4[4];
                ldsm4(t4, stg + OFF_BH + bo);
                bh[2 * j2][0] = t4[0]; bh[2 * j2][1] = t4[1];
                bh[2 * j2 + 1][0] = t4[2]; bh[2 * j2 + 1][1] = t4[3];
                ldsm4(t4, stg + OFF_BL + bo);
                bl[2 * j2][0] = t4[0]; bl[2 * j2][1] = t4[1];
                bl[2 * j2 + 1][0] = t4[2]; bl[2 * j2 + 1][1] = t4[3];
            }
#pragma unroll
            for (int i = 0; i < 2; i++)
#pragma unroll
                for (int j = 0; j < 4; j++) {
                    mma16816(acc[i][j], ah[i], bh[j]);
                    mma16816(acc[i][j], al[i], bh[j]);
                    mma16816(acc[i][j], ah[i], bl[j]);
                }
        }
        __syncthreads();
        slot = (slot + 1) % 3;
    }

#pragma unroll
    for (int i = 0; i < 2; i++) {
        int row0 = wm + i * 16 + (lane >> 2);
        int tok0 = (m0 + row0 < cnt) ? g_tok[e * T_TOK + m0 + row0] : -1;
        int tok1 = (m0 + row0 + 8 < cnt) ? g_tok[e * T_TOK + m0 + row0 + 8] : -1;
        float w0 = (tok0 >= 0) ? g_w[tok0] : 0.0f;
        float w1 = (tok1 >= 0) ? g_w[tok1] : 0.0f;
#pragma unroll
        for (int j = 0; j < 4; j++) {
            int col = n0 + wn + j * 8 + 2 * (lane & 3);
            float b0 = __ldg(bout + (size_t)e * DIM + col);
            float b1 = __ldg(bout + (size_t)e * DIM + col + 1);
            if (tok0 >= 0) {
                float2 v = make_float2(w0 * (acc[i][j][0] + b0), w0 * (acc[i][j][1] + b1));
                *(float2*)(out + (size_t)tok0 * DIM + col) = v;
            }
            if (tok1 >= 0) {
                float2 v = make_float2(w1 * (acc[i][j][2] + b0), w1 * (acc[i][j][3] + b1));
                *(float2*)(out + (size_t)tok1 * DIM + col) = v;
            }
        }
    }
}

// ---------------- launch ------------------------------------------------------
extern "C" void kernel_launch(void* const* d_in, const int* in_sizes, int n_in,
                              void* d_out, int out_size) {
    const float* x    = (const float*)d_in[0];
    const float* Wg   = (const float*)d_in[1];
    const float* bg   = (const float*)d_in[2];
    const float* Wfc  = (const float*)d_in[3];
    const float* bfc  = (const float*)d_in[4];
    const float* Wout = (const float*)d_in[5];
    const float* bout = (const float*)d_in[6];
    float* out = (float*)d_out;

    cudaFuncSetAttribute(k_ffn1, cudaFuncAttributeMaxDynamicSharedMemorySize, SMEM_DYN);
    cudaFuncSetAttribute(k_ffn2, cudaFuncAttributeMaxDynamicSharedMemorySize, SMEM_DYN);

    __nv_bfloat16 *w1h, *w1l, *w2h, *w2l;
    cudaGetSymbolAddress((void**)&w1h, s_w1hi);
    cudaGetSymbolAddress((void**)&w1l, s_w1lo);
    cudaGetSymbolAddress((void**)&w2h, s_w2hi);
    cudaGetSymbolAddress((void**)&w2l, s_w2lo);

    // Launch order keeps k_ffn1 as the 4th launch (ncu capture slot).
    k_init<<<1, 32>>>();                                   // 1
    k_gate<<<T_TOK / 8, 256>>>(x, Wg, bg);                 // 2 (gating + x hi/lo)
    {
        dim3 b(256);
        dim3 gw1(TWOF / 32, DIM / 32, NEXP);
        k_cvt_w<<<gw1, b>>>(Wfc, w1h, w1l, DIM, TWOF);     // 3
    }
    dim3 g1(T_TOK / 64, FDIM / 64, NEXP);                  // (128, 64, 8)
    k_ffn1<<<g1, 256, SMEM_DYN>>>(bfc);                    // 4  <-- profiled
    k_loss<<<1, 32>>>(out, out_size);                      // 5
    {
        dim3 b(256);
        dim3 gw2(DIM / 32, FDIM / 32, NEXP);
        k_cvt_w<<<gw2, b>>>(Wout, w2h, w2l, FDIM, DIM);    // 6
    }
    dim3 g2(T_TOK / 64, DIM / 128, NEXP);                  // (128, 8, 8)
    k_ffn2<<<g2, 256, SMEM_DYN>>>(bout, out);              // 7
}